// round 10
// baseline (speedup 1.0000x reference)
#include <cuda_runtime.h>
#include <cuda_fp16.h>
#include <cstdint>

// RBF: out[n] = sum_m w[m]*exp(-dist), dist = sum_k A[n,k]B[m,k], K=561->576.
// mma.sync.m16n8k16 fp16, 2-limb split, 3 limb passes (00,01,10).
// Round 10: ldmatrix.x4 fragment loads (72 LDS.32 -> 18 LDSM per warp-chunk),
// 4-stage cp.async ring with ONE __syncthreads per chunk, 96KB dynamic smem.

#define DD 32
#define NN 32768
#define MM 2048
#define KS 576
#define KCH 16
#define NCHK 36
#define CSTR 24            // halfs; 48B row stride, conflict-free for ldmatrix
#define PL (128 * CSTR)    // halfs per plane
#define STB (4 * PL * 2)   // bytes per stage (4 planes) = 24576
#define NSTG 4
#define DSMEM (NSTG * STB) // 98304

__device__ __half g_A[(size_t)NN * 2 * KS];
__device__ __half g_B[(size_t)MM * 2 * KS];
__device__ int g_tabD[KS];
__device__ int g_tabE[KS];

// ---- helpers ---------------------------------------------------------------
__device__ __forceinline__ void split2(float f, __half& h0, __half& h1) {
    h0 = __float2half_rn(f);
    h1 = __float2half_rn(f - __half2float(h0));
}
__device__ __forceinline__ void mma16816(float* c, const uint32_t* a,
                                         const uint32_t* b) {
    asm("mma.sync.aligned.m16n8k16.row.col.f32.f16.f16.f32 "
        "{%0,%1,%2,%3}, {%4,%5,%6,%7}, {%8,%9}, {%0,%1,%2,%3};"
        : "+f"(c[0]), "+f"(c[1]), "+f"(c[2]), "+f"(c[3])
        : "r"(a[0]), "r"(a[1]), "r"(a[2]), "r"(a[3]), "r"(b[0]), "r"(b[1]));
}
__device__ __forceinline__ void cp16(uint32_t dst, const void* src) {
    asm volatile("cp.async.cg.shared.global [%0], [%1], 16;" ::"r"(dst), "l"(src));
}
#define LDSM4(r, addr)                                                    \
    asm volatile(                                                         \
        "ldmatrix.sync.aligned.m8n8.x4.shared.b16 {%0,%1,%2,%3}, [%4];"   \
        : "=r"((r)[0]), "=r"((r)[1]), "=r"((r)[2]), "=r"((r)[3])          \
        : "r"(addr))

// ---- Kernel 0: triangle index tables --------------------------------------
__global__ void prep_tri_kernel() {
    int k = threadIdx.x;
    if (k < 528) {
        int d = 0, rem = k;
        while (rem >= DD - d) { rem -= DD - d; d++; }
        g_tabD[k] = d;
        g_tabE[k] = d + rem;
    } else {
        g_tabD[k] = 0;
        g_tabE[k] = 0;
    }
}

// ---- Prep A: per-n features, one warp per n -------------------------------
__global__ __launch_bounds__(128) void prep_a_kernel(const float* __restrict__ x) {
    const int warp = threadIdx.x / 32, lane = threadIdx.x % 32;
    const int n = blockIdx.x * 4 + warp;
    const float xv = x[(size_t)n * DD + lane];
    __half* o0 = g_A + ((size_t)n * 2 + 0) * KS;
    __half* o1 = g_A + ((size_t)n * 2 + 1) * KS;

#pragma unroll 1
    for (int j = 0; j < KS / 32; j++) {
        const int k = j * 32 + lane;
        const int d = __ldg(&g_tabD[k]);
        const int e = __ldg(&g_tabE[k]);
        float fd = __shfl_sync(0xFFFFFFFFu, xv, d);
        float fe = __shfl_sync(0xFFFFFFFFu, xv, e);
        float f;
        if (k < 528) f = fd * fe;
        else if (k < 560) f = __shfl_sync(0xFFFFFFFFu, xv, k - 528);
        else if (k == 560) f = 1.0f;
        else f = 0.0f;
        __half h0, h1;
        split2(f, h0, h1);
        o0[k] = h0;
        o1[k] = h1;
    }
}

// ---- Prep B: per-m features, one CTA per m --------------------------------
__global__ __launch_bounds__(128) void prep_b_kernel(const float* __restrict__ gamma,
                                                     const float* __restrict__ means) {
    __shared__ float Gs[DD * DD];
    __shared__ float mus[DD];
    __shared__ float sv[DD];
    __shared__ float bv[DD];
    __shared__ float cval;

    const int m = blockIdx.x;
    const int tid = threadIdx.x;
    const float* gsrc = gamma + (size_t)m * DD * DD;
#pragma unroll
    for (int i = tid; i < DD * DD; i += 128) Gs[i] = gsrc[i];
    if (tid < DD) mus[tid] = means[(size_t)m * DD + tid];
    __syncthreads();

    if (tid < DD) {
        float s = 0.0f;
#pragma unroll
        for (int e = 0; e < DD; e++) s += mus[e] * Gs[e * DD + tid];
        sv[tid] = s;
    }
    __syncthreads();
    if (tid < DD) {
        float b = 0.0f;
#pragma unroll
        for (int k = 0; k < DD; k++) b += Gs[tid * DD + k] * sv[k];
        bv[tid] = b;
    }
    __syncthreads();
    if (tid == 0) {
        float c = 0.0f;
#pragma unroll
        for (int d = 0; d < DD; d++) c += bv[d] * mus[d];
        cval = c;
    }
    __syncthreads();

    __half* o0 = g_B + ((size_t)m * 2 + 0) * KS;
    __half* o1 = g_B + ((size_t)m * 2 + 1) * KS;
    for (int k = tid; k < KS; k += 128) {
        float f;
        if (k < 528) {
            const int d = g_tabD[k], e = g_tabE[k];
            float cde = 0.0f;
#pragma unroll
            for (int q = 0; q < DD; q++) cde += Gs[d * DD + q] * Gs[e * DD + q];
            f = (d == e) ? cde : 2.0f * cde;
        } else if (k < 560) {
            f = -2.0f * bv[k - 528];
        } else if (k == 560) {
            f = cval;
        } else {
            f = 0.0f;
        }
        __half h0, h1;
        split2(f, h0, h1);
        o0[k] = h0;
        o1[k] = h1;
    }
}

// ---- Main: 128n x 128m tiles, 4-stage pipeline, ldmatrix frags ------------
__global__ __launch_bounds__(256, 1) void rbf_mma_kernel(const float* __restrict__ w,
                                                         float* __restrict__ out) {
    extern __shared__ __align__(16) unsigned char dsm[];
    const int tid = threadIdx.x;
    const int warp = tid >> 5, lane = tid & 31;
    const int n0 = blockIdx.x * 128;
    const uint32_t smem = (uint32_t)__cvta_generic_to_shared(dsm);

    // cp.async mapping: 4 planes x 256 real 16B units per plane
    const int lp = tid >> 6;   // plane
    const int lu = tid & 63;   // 4 units each

    // ldmatrix lane offsets (bytes within plane)
    const int rloc = lane & 7;
    const int rowblk = (lane >> 3) & 1;
    const int half8 = (lane >> 4) & 1;
    const uint32_t a_off = (uint32_t)(((warp * 16 + rowblk * 8 + rloc) * CSTR + half8 * 8) * 2);
    // B: jsel=(lane>>4)&1 selects j within pair, kh=(lane>>3)&1 selects k-half
    const uint32_t b_off = (uint32_t)((((lane >> 4 & 1) * 8 + rloc) * CSTR + (lane >> 3 & 1) * 8) * 2);

    float accR0 = 0.0f, accR1 = 0.0f;

    for (int mb = 0; mb < MM / 128; mb++) {
        float c[16][4];
#pragma unroll
        for (int j = 0; j < 16; j++) {
            c[j][0] = 0.0f; c[j][1] = 0.0f; c[j][2] = 0.0f; c[j][3] = 0.0f;
        }

        // stage-issue lambda
        auto issue = [&](int chunk) {
            const int buf = chunk & 3;
            const int ko = chunk * KCH;
            const uint32_t dstb = smem + buf * STB + lp * PL * 2;
#pragma unroll
            for (int q = 0; q < 4; q++) {
                const int unit = lu * 4 + q;
                const int row = unit >> 1, h = unit & 1;
                const uint32_t dst = dstb + (uint32_t)((row * CSTR + h * 8) * 2);
                const __half* src =
                    (lp < 2) ? g_A + ((size_t)(n0 + row) * 2 + lp) * KS + ko + h * 8
                             : g_B + ((size_t)(mb * 128 + row) * 2 + (lp - 2)) * KS + ko + h * 8;
                cp16(dst, src);
            }
            asm volatile("cp.async.commit_group;");
        };

        // prologue: chunks 0,1,2
        issue(0);
        issue(1);
        issue(2);

        for (int ch = 0; ch < NCHK; ch++) {
            if (ch <= NCHK - 3) asm volatile("cp.async.wait_group 2;");
            else if (ch == NCHK - 2) asm volatile("cp.async.wait_group 1;");
            else asm volatile("cp.async.wait_group 0;");
            __syncthreads();  // chunk ch ready; buffer (ch-1)&3 free for refill
            if (ch + 3 < NCHK) issue(ch + 3);

            const uint32_t sb = smem + (ch & 3) * STB;

            uint32_t afr[2][4];
            LDSM4(afr[0], sb + 0 * PL * 2 + a_off);
            LDSM4(afr[1], sb + 1 * PL * 2 + a_off);

#pragma unroll
            for (int jb = 0; jb < 2; jb++) {
                // B frags: 4 j-pairs per jb, both limbs. bfr[l][u] = {bj0_0,bj0_1,bj1_0,bj1_1}
                uint32_t bfr[2][4][4];
#pragma unroll
                for (int l = 0; l < 2; l++) {
#pragma unroll
                    for (int u = 0; u < 4; u++) {
                        const uint32_t addr = sb + (2 + l) * PL * 2 + b_off +
                                              (uint32_t)((jb * 4 + u) * 16 * CSTR * 2);
                        LDSM4(bfr[l][u], addr);
                    }
                }
                // 3 limb passes, 8 j's each: dependency chain distance 8
#pragma unroll
                for (int u = 0; u < 4; u++) {
                    mma16816(c[jb * 8 + 2 * u], afr[0], &bfr[0][u][0]);
                    mma16816(c[jb * 8 + 2 * u + 1], afr[0], &bfr[0][u][2]);
                }
#pragma unroll
                for (int u = 0; u < 4; u++) {
                    mma16816(c[jb * 8 + 2 * u], afr[0], &bfr[1][u][0]);
                    mma16816(c[jb * 8 + 2 * u + 1], afr[0], &bfr[1][u][2]);
                }
#pragma unroll
                for (int u = 0; u < 4; u++) {
                    mma16816(c[jb * 8 + 2 * u], afr[1], &bfr[0][u][0]);
                    mma16816(c[jb * 8 + 2 * u + 1], afr[1], &bfr[0][u][2]);
                }
            }
        }

        // Epilogue: acc += w * exp(-dist), predicated (fp32 exp == 0 beyond ~104)
#pragma unroll
        for (int j = 0; j < 16; j++) {
            const int col = mb * 128 + j * 8 + (lane & 3) * 2;
            const float w0 = __ldg(w + col), w1 = __ldg(w + col + 1);
            if (c[j][0] < 100.0f) accR0 += w0 * __expf(-c[j][0]);
            if (c[j][1] < 100.0f) accR0 += w1 * __expf(-c[j][1]);
            if (c[j][2] < 100.0f) accR1 += w0 * __expf(-c[j][2]);
            if (c[j][3] < 100.0f) accR1 += w1 * __expf(-c[j][3]);
        }
        // buffer 3 of this mb is protected by next mb's iter-0 __syncthreads
    }

    accR0 += __shfl_xor_sync(0xFFFFFFFFu, accR0, 1);
    accR0 += __shfl_xor_sync(0xFFFFFFFFu, accR0, 2);
    accR1 += __shfl_xor_sync(0xFFFFFFFFu, accR1, 1);
    accR1 += __shfl_xor_sync(0xFFFFFFFFu, accR1, 2);
    if ((lane & 3) == 0) {
        const int r = warp * 16 + (lane >> 2);
        out[n0 + r] = accR0;
        out[n0 + r + 8] = accR1;
    }
}

extern "C" void kernel_launch(void* const* d_in, const int* in_sizes, int n_in,
                              void* d_out, int out_size) {
    const float* inputs = (const float*)d_in[0];   // [N, D]
    const float* gamma = (const float*)d_in[1];    // [M, D, D]
    const float* means = (const float*)d_in[2];    // [M, D]
    const float* weights = (const float*)d_in[3];  // [M]
    float* out = (float*)d_out;                    // [N, 1]

    cudaFuncSetAttribute(rbf_mma_kernel, cudaFuncAttributeMaxDynamicSharedMemorySize,
                         DSMEM);

    prep_tri_kernel<<<1, KS>>>();
    prep_a_kernel<<<NN / 4, 128>>>(inputs);
    prep_b_kernel<<<MM, 128>>>(gamma, means);
    rbf_mma_kernel<<<NN / 128, 256, DSMEM>>>(weights, out);
}

// round 12
// speedup vs baseline: 1.2912x; 1.2912x over previous
#include <cuda_runtime.h>
#include <cuda_fp16.h>
#include <cstdint>

// RBF: out[n] = sum_m w[m]*exp(-dist), dist = sum_k A[n,k]B[m,k], K=561->576.
// mma.sync.m16n8k16 fp16, 2-limb split, 3 limb passes (00,01,10).
// Round 12 (= R11 resubmit after infra failure): 128n x 64m tiles ->
// 32 accum regs/thread, __launch_bounds__(256,2) => 2 CTAs (16 warps)/SM.
// 4-stage cp.async ring, 18KB/stage (72KB/CTA dynamic smem), ldmatrix.x4.

#define DD 32
#define NN 32768
#define MM 2048
#define KS 576
#define KCH 16
#define NCHK 36
#define MT 64               // m-tile
#define CSTR 24             // halfs; 48B row stride
#define PLA (128 * CSTR)    // A plane halfs
#define PLB (MT * CSTR)     // B plane halfs
#define STB ((2 * PLA + 2 * PLB) * 2)  // bytes per stage = 18432
#define NSTG 4
#define DSMEM (NSTG * STB)  // 73728

__device__ __half g_A[(size_t)NN * 2 * KS];
__device__ __half g_B[(size_t)MM * 2 * KS];
__device__ int g_tabD[KS];
__device__ int g_tabE[KS];

// ---- helpers ---------------------------------------------------------------
__device__ __forceinline__ void split2(float f, __half& h0, __half& h1) {
    h0 = __float2half_rn(f);
    h1 = __float2half_rn(f - __half2float(h0));
}
__device__ __forceinline__ void mma16816(float* c, const uint32_t* a,
                                         const uint32_t* b) {
    asm("mma.sync.aligned.m16n8k16.row.col.f32.f16.f16.f32 "
        "{%0,%1,%2,%3}, {%4,%5,%6,%7}, {%8,%9}, {%0,%1,%2,%3};"
        : "+f"(c[0]), "+f"(c[1]), "+f"(c[2]), "+f"(c[3])
        : "r"(a[0]), "r"(a[1]), "r"(a[2]), "r"(a[3]), "r"(b[0]), "r"(b[1]));
}
__device__ __forceinline__ void cp16(uint32_t dst, const void* src) {
    asm volatile("cp.async.cg.shared.global [%0], [%1], 16;" ::"r"(dst), "l"(src));
}
#define LDSM4(r, addr)                                                    \
    asm volatile(                                                         \
        "ldmatrix.sync.aligned.m8n8.x4.shared.b16 {%0,%1,%2,%3}, [%4];"   \
        : "=r"((r)[0]), "=r"((r)[1]), "=r"((r)[2]), "=r"((r)[3])          \
        : "r"(addr))

// Stage fill: 768 16B units (A: 512, B: 256), 3 per thread.
__device__ __forceinline__ void issue_stage(uint32_t smem, int chunk, int n0,
                                            int mb, int tid) {
    const uint32_t stg = smem + (chunk & 3) * STB;
    const int ko = chunk * KCH;
    const uint32_t pA0 = 0, pA1 = PLA * 2, pB0 = 2 * PLA * 2,
                   pB1 = 2 * PLA * 2 + PLB * 2;
#pragma unroll
    for (int q = 0; q < 3; q++) {
        const int unit = tid + 256 * q;
        if (unit < 512) {
            const int limb = unit >> 8;
            const int row = (unit & 255) >> 1, h = unit & 1;
            cp16(stg + (limb ? pA1 : pA0) + (uint32_t)((row * CSTR + h * 8) * 2),
                 g_A + ((size_t)(n0 + row) * 2 + limb) * KS + ko + h * 8);
        } else {
            const int u = unit - 512;
            const int limb = u >> 7;
            const int row = (u & 127) >> 1, h = u & 1;
            cp16(stg + (limb ? pB1 : pB0) + (uint32_t)((row * CSTR + h * 8) * 2),
                 g_B + ((size_t)(mb * MT + row) * 2 + limb) * KS + ko + h * 8);
        }
    }
    asm volatile("cp.async.commit_group;");
}

// ---- Kernel 0: triangle index tables --------------------------------------
__global__ void prep_tri_kernel() {
    int k = threadIdx.x;
    if (k < 528) {
        int d = 0, rem = k;
        while (rem >= DD - d) { rem -= DD - d; d++; }
        g_tabD[k] = d;
        g_tabE[k] = d + rem;
    } else {
        g_tabD[k] = 0;
        g_tabE[k] = 0;
    }
}

// ---- Prep A: per-n features, one warp per n -------------------------------
__global__ __launch_bounds__(128) void prep_a_kernel(const float* __restrict__ x) {
    const int warp = threadIdx.x / 32, lane = threadIdx.x % 32;
    const int n = blockIdx.x * 4 + warp;
    const float xv = x[(size_t)n * DD + lane];
    __half* o0 = g_A + ((size_t)n * 2 + 0) * KS;
    __half* o1 = g_A + ((size_t)n * 2 + 1) * KS;

#pragma unroll 1
    for (int j = 0; j < KS / 32; j++) {
        const int k = j * 32 + lane;
        const int d = __ldg(&g_tabD[k]);
        const int e = __ldg(&g_tabE[k]);
        float fd = __shfl_sync(0xFFFFFFFFu, xv, d);
        float fe = __shfl_sync(0xFFFFFFFFu, xv, e);
        float f;
        if (k < 528) f = fd * fe;
        else if (k < 560) f = __shfl_sync(0xFFFFFFFFu, xv, k - 528);
        else if (k == 560) f = 1.0f;
        else f = 0.0f;
        __half h0, h1;
        split2(f, h0, h1);
        o0[k] = h0;
        o1[k] = h1;
    }
}

// ---- Prep B: per-m features, one CTA per m --------------------------------
__global__ __launch_bounds__(128) void prep_b_kernel(const float* __restrict__ gamma,
                                                     const float* __restrict__ means) {
    __shared__ float Gs[DD * DD];
    __shared__ float mus[DD];
    __shared__ float sv[DD];
    __shared__ float bv[DD];
    __shared__ float cval;

    const int m = blockIdx.x;
    const int tid = threadIdx.x;
    const float* gsrc = gamma + (size_t)m * DD * DD;
#pragma unroll
    for (int i = tid; i < DD * DD; i += 128) Gs[i] = gsrc[i];
    if (tid < DD) mus[tid] = means[(size_t)m * DD + tid];
    __syncthreads();

    if (tid < DD) {
        float s = 0.0f;
#pragma unroll
        for (int e = 0; e < DD; e++) s += mus[e] * Gs[e * DD + tid];
        sv[tid] = s;
    }
    __syncthreads();
    if (tid < DD) {
        float b = 0.0f;
#pragma unroll
        for (int k = 0; k < DD; k++) b += Gs[tid * DD + k] * sv[k];
        bv[tid] = b;
    }
    __syncthreads();
    if (tid == 0) {
        float c = 0.0f;
#pragma unroll
        for (int d = 0; d < DD; d++) c += bv[d] * mus[d];
        cval = c;
    }
    __syncthreads();

    __half* o0 = g_B + ((size_t)m * 2 + 0) * KS;
    __half* o1 = g_B + ((size_t)m * 2 + 1) * KS;
    for (int k = tid; k < KS; k += 128) {
        float f;
        if (k < 528) {
            const int d = g_tabD[k], e = g_tabE[k];
            float cde = 0.0f;
#pragma unroll
            for (int q = 0; q < DD; q++) cde += Gs[d * DD + q] * Gs[e * DD + q];
            f = (d == e) ? cde : 2.0f * cde;
        } else if (k < 560) {
            f = -2.0f * bv[k - 528];
        } else if (k == 560) {
            f = cval;
        } else {
            f = 0.0f;
        }
        __half h0, h1;
        split2(f, h0, h1);
        o0[k] = h0;
        o1[k] = h1;
    }
}

// ---- Main: 128n x 64m tiles, 2 CTAs/SM, 4-stage pipeline ------------------
__global__ __launch_bounds__(256, 2) void rbf_mma_kernel(const float* __restrict__ w,
                                                         float* __restrict__ out) {
    extern __shared__ __align__(16) unsigned char dsm[];
    const int tid = threadIdx.x;
    const int warp = tid >> 5, lane = tid & 31;
    const int n0 = blockIdx.x * 128;
    const uint32_t smem = (uint32_t)__cvta_generic_to_shared(dsm);

    const uint32_t pA0 = 0, pA1 = PLA * 2, pB0 = 2 * PLA * 2,
                   pB1 = 2 * PLA * 2 + PLB * 2;

    // ldmatrix lane offsets (bytes within plane)
    const int rloc = lane & 7;
    const uint32_t a_off =
        (uint32_t)(((warp * 16 + ((lane >> 3) & 1) * 8 + rloc) * CSTR +
                    ((lane >> 4) & 1) * 8) * 2);
    const uint32_t b_off =
        (uint32_t)(((((lane >> 4) & 1) * 8 + rloc) * CSTR + ((lane >> 3) & 1) * 8) * 2);

    float accR0 = 0.0f, accR1 = 0.0f;

    for (int mb = 0; mb < MM / MT; mb++) {
        float c[8][4];
#pragma unroll
        for (int j = 0; j < 8; j++) {
            c[j][0] = 0.0f; c[j][1] = 0.0f; c[j][2] = 0.0f; c[j][3] = 0.0f;
        }

        issue_stage(smem, 0, n0, mb, tid);
        issue_stage(smem, 1, n0, mb, tid);
        issue_stage(smem, 2, n0, mb, tid);

        for (int ch = 0; ch < NCHK; ch++) {
            if (ch <= NCHK - 3) asm volatile("cp.async.wait_group 2;");
            else if (ch == NCHK - 2) asm volatile("cp.async.wait_group 1;");
            else asm volatile("cp.async.wait_group 0;");
            __syncthreads();
            if (ch + 3 < NCHK) issue_stage(smem, ch + 3, n0, mb, tid);

            const uint32_t stg = smem + (ch & 3) * STB;

            uint32_t afr[2][4];
            LDSM4(afr[0], stg + pA0 + a_off);
            LDSM4(afr[1], stg + pA1 + a_off);

            // B frags: u in 0..3 covers rows u*16+[0,16) = j pair (2u, 2u+1)
            uint32_t bfr[2][4][4];
#pragma unroll
            for (int u = 0; u < 4; u++)
                LDSM4(bfr[0][u], stg + pB0 + b_off + (uint32_t)(u * 16 * CSTR * 2));
#pragma unroll
            for (int u = 0; u < 4; u++)
                LDSM4(bfr[1][u], stg + pB1 + b_off + (uint32_t)(u * 16 * CSTR * 2));

            // 3 limb passes, 8 j's each: chain distance 8
#pragma unroll
            for (int u = 0; u < 4; u++) {
                mma16816(c[2 * u], afr[0], &bfr[0][u][0]);
                mma16816(c[2 * u + 1], afr[0], &bfr[0][u][2]);
            }
#pragma unroll
            for (int u = 0; u < 4; u++) {
                mma16816(c[2 * u], afr[0], &bfr[1][u][0]);
                mma16816(c[2 * u + 1], afr[0], &bfr[1][u][2]);
            }
#pragma unroll
            for (int u = 0; u < 4; u++) {
                mma16816(c[2 * u], afr[1], &bfr[0][u][0]);
                mma16816(c[2 * u + 1], afr[1], &bfr[0][u][2]);
            }
        }

        // Epilogue: acc += w * exp(-dist), predicated (fp32 exp == 0 beyond ~104)
#pragma unroll
        for (int j = 0; j < 8; j++) {
            const int col = mb * MT + j * 8 + (lane & 3) * 2;
            const float w0 = __ldg(w + col), w1 = __ldg(w + col + 1);
            if (c[j][0] < 100.0f) accR0 += w0 * __expf(-c[j][0]);
            if (c[j][1] < 100.0f) accR0 += w1 * __expf(-c[j][1]);
            if (c[j][2] < 100.0f) accR1 += w0 * __expf(-c[j][2]);
            if (c[j][3] < 100.0f) accR1 += w1 * __expf(-c[j][3]);
        }
    }

    accR0 += __shfl_xor_sync(0xFFFFFFFFu, accR0, 1);
    accR0 += __shfl_xor_sync(0xFFFFFFFFu, accR0, 2);
    accR1 += __shfl_xor_sync(0xFFFFFFFFu, accR1, 1);
    accR1 += __shfl_xor_sync(0xFFFFFFFFu, accR1, 2);
    if ((lane & 3) == 0) {
        const int r = warp * 16 + (lane >> 2);
        out[n0 + r] = accR0;
        out[n0 + r + 8] = accR1;
    }
}

extern "C" void kernel_launch(void* const* d_in, const int* in_sizes, int n_in,
                              void* d_out, int out_size) {
    const float* inputs = (const float*)d_in[0];   // [N, D]
    const float* gamma = (const float*)d_in[1];    // [M, D, D]
    const float* means = (const float*)d_in[2];    // [M, D]
    const float* weights = (const float*)d_in[3];  // [M]
    float* out = (float*)d_out;                    // [N, 1]

    cudaFuncSetAttribute(rbf_mma_kernel, cudaFuncAttributeMaxDynamicSharedMemorySize,
                         DSMEM);

    prep_tri_kernel<<<1, KS>>>();
    prep_a_kernel<<<NN / 4, 128>>>(inputs);
    prep_b_kernel<<<MM, 128>>>(gamma, means);
    rbf_mma_kernel<<<NN / 128, 256, DSMEM>>>(weights, out);
}

// round 13
// speedup vs baseline: 2.9683x; 2.2988x over previous
#include <cuda_runtime.h>
#include <cuda_fp16.h>
#include <cstdint>

// RBF: out[n] = sum_m w[m]*exp(-dist(n,m)). Screen-then-refine:
//  1) fp16 single-pass GEMM (K=576 expanded features) -> approx dist (+-~20).
//     approx < 128 => survivor bit in g_mask (superset of true dist<100;
//     dist>=100 contributes exactly 0 in fp32, validated since R8).
//  2) per-n warp scans mask, evaluates exact fp32 dist via R5 triangle blob
//     for survivors only, accumulates w*exp(-dist).

#define DD 32
#define NN 32768
#define MM 2048
#define KS 576
#define KCH 48
#define NCHK 12
#define MT 64
#define CSTR 56                 // halfs; 112B row stride, conflict-free ldmatrix
#define PLA (128 * CSTR)
#define PLB (MT * CSTR)
#define STB ((PLA + PLB) * 2)   // 21504 B/stage
#define NSTG 4
#define DSMEM (NSTG * STB)      // 86016
#define TH 128.0f
#define BLOB 640

__device__ __align__(16) __half g_A[(size_t)NN * KS];      // 37.7 MB
__device__ __align__(16) __half g_B[(size_t)MM * KS];
__device__ __align__(16) float g_blob[(size_t)MM * BLOB];  // R5 triangle blobs
__device__ uint32_t g_mask[(size_t)NN * (MM / 32)];        // 8.4 MB
__device__ int g_tabD[KS];
__device__ int g_tabE[KS];
__device__ int g_rs[DD];  // rowstart table for blob layout

__host__ __device__ constexpr int padlen(int d) { return ((DD - d + 3) / 4) * 4; }
__host__ __device__ constexpr int rowstart(int d) {
    int s = 0;
    for (int k = 0; k < d; k++) s += padlen(k);
    return s;  // rowstart(32) == 576
}

// ---- helpers ---------------------------------------------------------------
__device__ __forceinline__ void mma16816(float* c, const uint32_t* a,
                                         const uint32_t* b) {
    asm("mma.sync.aligned.m16n8k16.row.col.f32.f16.f16.f32 "
        "{%0,%1,%2,%3}, {%4,%5,%6,%7}, {%8,%9}, {%0,%1,%2,%3};"
        : "+f"(c[0]), "+f"(c[1]), "+f"(c[2]), "+f"(c[3])
        : "r"(a[0]), "r"(a[1]), "r"(a[2]), "r"(a[3]), "r"(b[0]), "r"(b[1]));
}
__device__ __forceinline__ void cp16(uint32_t dst, const void* src) {
    asm volatile("cp.async.cg.shared.global [%0], [%1], 16;" ::"r"(dst), "l"(src));
}
#define LDSM4(r, addr)                                                    \
    asm volatile(                                                         \
        "ldmatrix.sync.aligned.m8n8.x4.shared.b16 {%0,%1,%2,%3}, [%4];"   \
        : "=r"((r)[0]), "=r"((r)[1]), "=r"((r)[2]), "=r"((r)[3])          \
        : "r"(addr))

// ---- Kernel 0: index tables ------------------------------------------------
__global__ void prep_tri_kernel() {
    int k = threadIdx.x;
    if (k < 528) {
        int d = 0, rem = k;
        while (rem >= DD - d) { rem -= DD - d; d++; }
        g_tabD[k] = d;
        g_tabE[k] = d + rem;
    } else if (k < KS) {
        g_tabD[k] = 0;
        g_tabE[k] = 0;
    }
    if (k < DD) {
        int s = 0;
        for (int q = 0; q < k; q++) s += padlen(q);
        g_rs[k] = s;
    }
}

// ---- Kernel 1: R5 blob (triangle w/ doubled off-diag, bm2, c) -------------
__global__ __launch_bounds__(128) void prep_blob_kernel(
    const float* __restrict__ gamma, const float* __restrict__ means) {
    __shared__ float Gs[DD * DD];
    __shared__ float Cs[DD * DD];
    __shared__ float mus[DD];
    __shared__ float bs[DD];

    const int m = blockIdx.x;
    const int tid = threadIdx.x;
    float* blob = g_blob + (size_t)m * BLOB;

    const float* gsrc = gamma + (size_t)m * DD * DD;
#pragma unroll
    for (int i = tid; i < DD * DD; i += 128) Gs[i] = gsrc[i];
    if (tid < DD) mus[tid] = means[(size_t)m * DD + tid];
    for (int i = tid; i < BLOB; i += 128) blob[i] = 0.0f;
    __syncthreads();

    for (int idx = tid; idx < 528; idx += 128) {
        int d = 0, rem = idx;
        while (rem >= DD - d) { rem -= DD - d; d++; }
        int e = d + rem;
        float c = 0.0f;
#pragma unroll
        for (int k = 0; k < DD; k++) c += Gs[d * DD + k] * Gs[e * DD + k];
        Cs[d * DD + e] = c;
        Cs[e * DD + d] = c;
        int rs = 0;
        for (int k = 0; k < d; k++) rs += padlen(k);
        blob[rs + (e - d)] = (e == d) ? c : 2.0f * c;
    }
    __syncthreads();

    if (tid < DD) {
        float b = 0.0f;
#pragma unroll
        for (int e = 0; e < DD; e++) b += Cs[tid * DD + e] * mus[e];
        bs[tid] = b;
        blob[576 + tid] = -2.0f * b;
    }
    __syncthreads();

    if (tid == 0) {
        float c = 0.0f;
#pragma unroll
        for (int d = 0; d < DD; d++) c += bs[d] * mus[d];
        blob[608] = c;
    }
}

// ---- Kernel 2: A features in fp16 (single limb), one warp per n -----------
__global__ __launch_bounds__(128) void prep_a_kernel(const float* __restrict__ x) {
    const int warp = threadIdx.x / 32, lane = threadIdx.x % 32;
    const int n = blockIdx.x * 4 + warp;
    const float xv = x[(size_t)n * DD + lane];
    __half* o = g_A + (size_t)n * KS;

#pragma unroll 1
    for (int j = 0; j < KS / 32; j++) {
        const int k = j * 32 + lane;
        const int d = __ldg(&g_tabD[k]);
        const int e = __ldg(&g_tabE[k]);
        float fd = __shfl_sync(0xFFFFFFFFu, xv, d);
        float fe = __shfl_sync(0xFFFFFFFFu, xv, e);
        float f;
        if (k < 528) f = fd * fe;
        else if (k < 560) f = __shfl_sync(0xFFFFFFFFu, xv, k - 528);
        else if (k == 560) f = 1.0f;
        else f = 0.0f;
        o[k] = __float2half_rn(f);
    }
}

// ---- Kernel 3: B features in fp16 from the blob ---------------------------
__global__ __launch_bounds__(128) void prep_b_kernel() {
    const int m = blockIdx.x;
    const int tid = threadIdx.x;
    const float* blob = g_blob + (size_t)m * BLOB;
    __half* o = g_B + (size_t)m * KS;
    for (int k = tid; k < KS; k += 128) {
        float f;
        if (k < 528) {
            const int d = g_tabD[k], e = g_tabE[k];
            f = blob[g_rs[d] + (e - d)];
        } else if (k < 560) {
            f = blob[576 + (k - 528)];
        } else if (k == 560) {
            f = blob[608];
        } else {
            f = 0.0f;
        }
        o[k] = __float2half_rn(f);
    }
}

// ---- Kernel 4: zero the survivor mask -------------------------------------
__global__ void zero_mask_kernel() {
    const size_t i = (size_t)blockIdx.x * 1024 + threadIdx.x;
    g_mask[i] = 0u;
}

// ---- Kernel 5: screening GEMM (fp16 single pass) --------------------------
__global__ __launch_bounds__(256, 2) void screen_kernel() {
    extern __shared__ __align__(16) unsigned char dsm[];
    const int tid = threadIdx.x;
    const int warp = tid >> 5, lane = tid & 31;
    const int n0 = blockIdx.x * 128;
    const uint32_t smem = (uint32_t)__cvta_generic_to_shared(dsm);

    const int rloc = lane & 7;
    const uint32_t a_off =
        (uint32_t)(((warp * 16 + ((lane >> 3) & 1) * 8 + rloc) * CSTR +
                    ((lane >> 4) & 1) * 8) * 2);
    const uint32_t b_off =
        (uint32_t)(((((lane >> 4) & 1) * 8 + rloc) * CSTR + ((lane >> 3) & 1) * 8) * 2);

    for (int mb = 0; mb < MM / MT; mb++) {
        float c[8][4];
#pragma unroll
        for (int j = 0; j < 8; j++) {
            c[j][0] = 0.0f; c[j][1] = 0.0f; c[j][2] = 0.0f; c[j][3] = 0.0f;
        }

        // stage fill: 1152 16B units (A:768, B:384)
        auto issue = [&](int chunk) {
            const uint32_t stg = smem + (chunk & 3) * STB;
            const int ko = chunk * KCH;
#pragma unroll
            for (int q = 0; q < 5; q++) {
                const int unit = tid + 256 * q;
                if (unit < 1152) {
                    const int row = unit / 6, h = unit % 6;
                    if (row < 128) {
                        cp16(stg + (uint32_t)((row * CSTR + h * 8) * 2),
                             g_A + (size_t)(n0 + row) * KS + ko + h * 8);
                    } else {
                        const int r = row - 128;
                        cp16(stg + PLA * 2 + (uint32_t)((r * CSTR + h * 8) * 2),
                             g_B + (size_t)(mb * MT + r) * KS + ko + h * 8);
                    }
                }
            }
            asm volatile("cp.async.commit_group;");
        };

        issue(0);
        issue(1);
        issue(2);

        for (int ch = 0; ch < NCHK; ch++) {
            if (ch <= NCHK - 3) asm volatile("cp.async.wait_group 2;");
            else if (ch == NCHK - 2) asm volatile("cp.async.wait_group 1;");
            else asm volatile("cp.async.wait_group 0;");
            __syncthreads();
            if (ch + 3 < NCHK) issue(ch + 3);

            const uint32_t stg = smem + (ch & 3) * STB;

#pragma unroll
            for (int kst = 0; kst < 3; kst++) {
                uint32_t afr[4];
                LDSM4(afr, stg + a_off + (uint32_t)(kst * 32));
                uint32_t bfr[4][4];
#pragma unroll
                for (int u = 0; u < 4; u++)
                    LDSM4(bfr[u], stg + PLA * 2 + b_off +
                                      (uint32_t)(u * 16 * CSTR * 2 + kst * 32));
#pragma unroll
                for (int u = 0; u < 4; u++) {
                    mma16816(c[2 * u], afr, &bfr[u][0]);
                    mma16816(c[2 * u + 1], afr, &bfr[u][2]);
                }
            }
        }

        // survivors -> mask bits
        const int r0 = n0 + warp * 16 + (lane >> 2);
#pragma unroll
        for (int j = 0; j < 8; j++) {
            const int col = mb * MT + j * 8 + (lane & 3) * 2;
            if (c[j][0] < TH)
                atomicOr(&g_mask[(size_t)r0 * 64 + (col >> 5)], 1u << (col & 31));
            if (c[j][1] < TH)
                atomicOr(&g_mask[(size_t)r0 * 64 + ((col + 1) >> 5)],
                         1u << ((col + 1) & 31));
            if (c[j][2] < TH)
                atomicOr(&g_mask[(size_t)(r0 + 8) * 64 + (col >> 5)], 1u << (col & 31));
            if (c[j][3] < TH)
                atomicOr(&g_mask[(size_t)(r0 + 8) * 64 + ((col + 1) >> 5)],
                         1u << ((col + 1) & 31));
        }
    }
}

// ---- Kernel 6: exact refine of survivors, one warp per n ------------------
__global__ __launch_bounds__(256) void refine_kernel(const float* __restrict__ x,
                                                     const float* __restrict__ w,
                                                     float* __restrict__ out) {
    const int warp = threadIdx.x >> 5, lane = threadIdx.x & 31;
    const int n = blockIdx.x * 8 + warp;

    float xr[DD];
    {
        const float4* xp = reinterpret_cast<const float4*>(x + (size_t)n * DD);
#pragma unroll
        for (int i = 0; i < DD / 4; i++) {
            float4 v = __ldg(xp + i);
            xr[4 * i] = v.x; xr[4 * i + 1] = v.y;
            xr[4 * i + 2] = v.z; xr[4 * i + 3] = v.w;
        }
    }

    float acc = 0.0f;
#pragma unroll 1
    for (int wi = 0; wi < 2; wi++) {
        const int widx = wi * 32 + lane;
        uint32_t word = g_mask[(size_t)n * 64 + widx];
        while (word) {
            const int b = __ffs(word) - 1;
            word &= word - 1;
            const int m = widx * 32 + b;
            const float* blob = g_blob + (size_t)m * BLOB;
            const float4* t4 = reinterpret_cast<const float4*>(blob);

            float dist = __ldg(blob + 608);
#pragma unroll
            for (int d = 0; d < DD; d++) {
                float t0 = 0.0f, t1 = 0.0f, t2 = 0.0f, t3 = 0.0f;
                const int ro4 = rowstart(d) / 4;
#pragma unroll
                for (int g = 0; g < padlen(d) / 4; g++) {
                    float4 v = __ldg(t4 + ro4 + g);
                    const int e0 = d + 4 * g;
                    t0 += v.x * xr[e0];
                    if (e0 + 1 < DD) t1 += v.y * xr[e0 + 1];
                    if (e0 + 2 < DD) t2 += v.z * xr[e0 + 2];
                    if (e0 + 3 < DD) t3 += v.w * xr[e0 + 3];
                }
                dist += xr[d] * ((t0 + t1) + (t2 + t3));
            }
#pragma unroll
            for (int g = 0; g < DD / 4; g++) {
                float4 v = __ldg(t4 + 144 + g);
                dist += v.x * xr[4 * g] + v.y * xr[4 * g + 1] +
                        v.z * xr[4 * g + 2] + v.w * xr[4 * g + 3];
            }
            if (dist < 100.0f) acc += __ldg(w + m) * __expf(-dist);
        }
    }

#pragma unroll
    for (int s = 16; s > 0; s >>= 1) acc += __shfl_xor_sync(0xFFFFFFFFu, acc, s);
    if (lane == 0) out[n] = acc;
}

extern "C" void kernel_launch(void* const* d_in, const int* in_sizes, int n_in,
                              void* d_out, int out_size) {
    const float* inputs = (const float*)d_in[0];   // [N, D]
    const float* gamma = (const float*)d_in[1];    // [M, D, D]
    const float* means = (const float*)d_in[2];    // [M, D]
    const float* weights = (const float*)d_in[3];  // [M]
    float* out = (float*)d_out;                    // [N, 1]

    cudaFuncSetAttribute(screen_kernel, cudaFuncAttributeMaxDynamicSharedMemorySize,
                         DSMEM);

    prep_tri_kernel<<<1, KS>>>();
    prep_blob_kernel<<<MM, 128>>>(gamma, means);
    prep_a_kernel<<<NN / 4, 128>>>(inputs);
    prep_b_kernel<<<MM, 128>>>();
    zero_mask_kernel<<<(NN * (MM / 32)) / 1024, 1024>>>();
    screen_kernel<<<NN / 128, 256, DSMEM>>>();
    refine_kernel<<<NN / 8, 256>>>(inputs, weights, out);
}

// round 14
// speedup vs baseline: 3.1785x; 1.0708x over previous
#include <cuda_runtime.h>
#include <cuda_fp16.h>
#include <cstdint>

// RBF: out[n] = sum_m w[m]*exp(-dist(n,m)). Screen-then-refine (R13 validated):
//  1) fp16 single-pass GEMM (K=576 features) -> approx dist; approx<128 =>
//     survivor bit (superset of true dist<100; dist>=100 contributes exact 0).
//  2) per-n warp refines survivors exactly in fp32 via triangle blob.
// Round 14: screen concurrency. 64-row n-tiles, 8 warps split over m halves,
// grid 512, KCH=32/CSTR=40, 4-stage ring (60KB) -> 3 CTAs/SM (24 warps/SM).
// prep_b fused into prep_blob; tables kill prep ALU loops.

#define DD 32
#define NN 32768
#define MM 2048
#define KS 576
#define KCH 32
#define NCHK 18
#define NT 64                   // n-tile rows
#define MT 64                   // m-tile rows
#define CSTR 40                 // halfs; 80B row stride, conflict-free ldmatrix
#define PLN (64 * CSTR)         // halfs per plane (A, B0, B1 all 64 rows)
#define STB (3 * PLN * 2)       // 15360 B/stage
#define NSTG 4
#define DSMEM (NSTG * STB)      // 61440
#define TH 128.0f
#define BLOB 640

__device__ __align__(16) __half g_A[(size_t)NN * KS];
__device__ __align__(16) __half g_B[(size_t)MM * KS];
__device__ __align__(16) float g_blob[(size_t)MM * BLOB];
__device__ uint32_t g_mask[(size_t)NN * (MM / 32)];
__device__ int g_tabD[KS];
__device__ int g_tabE[KS];
__device__ int g_rs[DD];

__host__ __device__ constexpr int padlen(int d) { return ((DD - d + 3) / 4) * 4; }
__host__ __device__ constexpr int rowstart(int d) {
    int s = 0;
    for (int k = 0; k < d; k++) s += padlen(k);
    return s;  // rowstart(32) == 576
}

// ---- helpers ---------------------------------------------------------------
__device__ __forceinline__ void mma16816(float* c, const uint32_t* a,
                                         const uint32_t* b) {
    asm("mma.sync.aligned.m16n8k16.row.col.f32.f16.f16.f32 "
        "{%0,%1,%2,%3}, {%4,%5,%6,%7}, {%8,%9}, {%0,%1,%2,%3};"
        : "+f"(c[0]), "+f"(c[1]), "+f"(c[2]), "+f"(c[3])
        : "r"(a[0]), "r"(a[1]), "r"(a[2]), "r"(a[3]), "r"(b[0]), "r"(b[1]));
}
__device__ __forceinline__ void cp16(uint32_t dst, const void* src) {
    asm volatile("cp.async.cg.shared.global [%0], [%1], 16;" ::"r"(dst), "l"(src));
}
#define LDSM4(r, addr)                                                    \
    asm volatile(                                                         \
        "ldmatrix.sync.aligned.m8n8.x4.shared.b16 {%0,%1,%2,%3}, [%4];"   \
        : "=r"((r)[0]), "=r"((r)[1]), "=r"((r)[2]), "=r"((r)[3])          \
        : "r"(addr))

// ---- Kernel 0: index tables ------------------------------------------------
__global__ void prep_tri_kernel() {
    int k = threadIdx.x;
    if (k < 528) {
        int d = 0, rem = k;
        while (rem >= DD - d) { rem -= DD - d; d++; }
        g_tabD[k] = d;
        g_tabE[k] = d + rem;
    } else if (k < KS) {
        g_tabD[k] = 0;
        g_tabE[k] = 0;
    }
    if (k < DD) {
        int s = 0;
        for (int q = 0; q < k; q++) s += padlen(q);
        g_rs[k] = s;
    }
}

// ---- Kernel 1: blob (fp32 triangle/bm2/c) + fp16 B row, fused -------------
__global__ __launch_bounds__(128) void prep_blob_kernel(
    const float* __restrict__ gamma, const float* __restrict__ means) {
    __shared__ float Gs[DD * DD];
    __shared__ float Cs[DD * DD];
    __shared__ float mus[DD];
    __shared__ float bs[DD];
    __shared__ float cvs;

    const int m = blockIdx.x;
    const int tid = threadIdx.x;
    float* blob = g_blob + (size_t)m * BLOB;
    __half* bout = g_B + (size_t)m * KS;

    const float* gsrc = gamma + (size_t)m * DD * DD;
#pragma unroll
    for (int i = tid; i < DD * DD; i += 128) Gs[i] = gsrc[i];
    if (tid < DD) mus[tid] = means[(size_t)m * DD + tid];
    for (int i = tid; i < BLOB; i += 128) blob[i] = 0.0f;
    for (int i = tid; i < KS; i += 128) bout[i] = __float2half_rn(0.0f);
    __syncthreads();

    for (int idx = tid; idx < 528; idx += 128) {
        const int d = g_tabD[idx], e = g_tabE[idx];
        float c = 0.0f;
#pragma unroll
        for (int k = 0; k < DD; k++) c += Gs[d * DD + k] * Gs[e * DD + k];
        Cs[d * DD + e] = c;
        Cs[e * DD + d] = c;
        const float v = (e == d) ? c : 2.0f * c;
        blob[g_rs[d] + (e - d)] = v;
        bout[idx] = __float2half_rn(v);  // feature order == tri linear order
    }
    __syncthreads();

    if (tid < DD) {
        float b = 0.0f;
#pragma unroll
        for (int e = 0; e < DD; e++) b += Cs[tid * DD + e] * mus[e];
        bs[tid] = b;
        blob[576 + tid] = -2.0f * b;
        bout[528 + tid] = __float2half_rn(-2.0f * b);
    }
    __syncthreads();

    if (tid == 0) {
        float c = 0.0f;
#pragma unroll
        for (int d = 0; d < DD; d++) c += bs[d] * mus[d];
        blob[608] = c;
        bout[560] = __float2half_rn(c);
    }
    (void)cvs;
}

// ---- Kernel 2: A features in fp16, one warp per n -------------------------
__global__ __launch_bounds__(128) void prep_a_kernel(const float* __restrict__ x) {
    const int warp = threadIdx.x / 32, lane = threadIdx.x % 32;
    const int n = blockIdx.x * 4 + warp;
    const float xv = x[(size_t)n * DD + lane];
    __half* o = g_A + (size_t)n * KS;

#pragma unroll 1
    for (int j = 0; j < KS / 32; j++) {
        const int k = j * 32 + lane;
        const int d = __ldg(&g_tabD[k]);
        const int e = __ldg(&g_tabE[k]);
        float fd = __shfl_sync(0xFFFFFFFFu, xv, d);
        float fe = __shfl_sync(0xFFFFFFFFu, xv, e);
        float f;
        if (k < 528) f = fd * fe;
        else if (k < 560) f = __shfl_sync(0xFFFFFFFFu, xv, k - 528);
        else if (k == 560) f = 1.0f;
        else f = 0.0f;
        o[k] = __float2half_rn(f);
    }
}

// ---- Kernel 3: zero the survivor mask -------------------------------------
__global__ void zero_mask_kernel() {
    const size_t i = (size_t)blockIdx.x * 1024 + threadIdx.x;
    g_mask[i] = 0u;
}

// ---- Kernel 4: screening GEMM ---------------------------------------------
// 64 n-rows per CTA; warps 0-3 rows x mb[0,16), warps 4-7 rows x mb[16,32).
__global__ __launch_bounds__(256, 3) void screen_kernel() {
    extern __shared__ __align__(16) unsigned char dsm[];
    const int tid = threadIdx.x;
    const int warp = tid >> 5, lane = tid & 31;
    const int wg = warp & 3;   // row group (16 rows)
    const int wh = warp >> 2;  // m half
    const int n0 = blockIdx.x * NT;
    const uint32_t smem = (uint32_t)__cvta_generic_to_shared(dsm);

    const int rloc = lane & 7;
    const uint32_t a_off =
        (uint32_t)(((wg * 16 + ((lane >> 3) & 1) * 8 + rloc) * CSTR +
                    ((lane >> 4) & 1) * 8) * 2);
    const uint32_t b_off =
        (uint32_t)(((((lane >> 4) & 1) * 8 + rloc) * CSTR + ((lane >> 3) & 1) * 8) * 2);
    const uint32_t b_plane = (uint32_t)((1 + wh) * PLN * 2);

    for (int mb = 0; mb < 16; mb++) {
        float c[8][4];
#pragma unroll
        for (int j = 0; j < 8; j++) {
            c[j][0] = 0.0f; c[j][1] = 0.0f; c[j][2] = 0.0f; c[j][3] = 0.0f;
        }

        // stage fill: 768 16B units (A:256, B0:256, B1:256), 3 per thread
        auto issue = [&](int chunk) {
            const uint32_t stg = smem + (chunk & 3) * STB;
            const int ko = chunk * KCH;
#pragma unroll
            for (int q = 0; q < 3; q++) {
                const int unit = tid + 256 * q;
                const int plane = unit >> 8;          // 0:A 1:B0 2:B1
                const int row = (unit & 255) >> 2, h = unit & 3;
                const uint32_t dst =
                    stg + (uint32_t)(plane * PLN * 2) + (uint32_t)((row * CSTR + h * 8) * 2);
                const __half* src =
                    (plane == 0)
                        ? g_A + (size_t)(n0 + row) * KS + ko + h * 8
                        : g_B + (size_t)(((mb + (plane - 1) * 16) * MT) + row) * KS + ko + h * 8;
                cp16(dst, src);
            }
            asm volatile("cp.async.commit_group;");
        };

        issue(0);
        issue(1);
        issue(2);

        for (int ch = 0; ch < NCHK; ch++) {
            if (ch <= NCHK - 3) asm volatile("cp.async.wait_group 2;");
            else if (ch == NCHK - 2) asm volatile("cp.async.wait_group 1;");
            else asm volatile("cp.async.wait_group 0;");
            __syncthreads();
            if (ch + 3 < NCHK) issue(ch + 3);

            const uint32_t stg = smem + (ch & 3) * STB;

#pragma unroll
            for (int kst = 0; kst < 2; kst++) {
                uint32_t afr[4];
                LDSM4(afr, stg + a_off + (uint32_t)(kst * 32));
                uint32_t bfr[4][4];
#pragma unroll
                for (int u = 0; u < 4; u++)
                    LDSM4(bfr[u], stg + b_plane + b_off +
                                      (uint32_t)(u * 16 * CSTR * 2 + kst * 32));
#pragma unroll
                for (int u = 0; u < 4; u++) {
                    mma16816(c[2 * u], afr, &bfr[u][0]);
                    mma16816(c[2 * u + 1], afr, &bfr[u][2]);
                }
            }
        }

        // survivors -> mask bits (disjoint col ranges across m halves)
        const int r0 = n0 + wg * 16 + (lane >> 2);
        const int mbe = mb + wh * 16;
#pragma unroll
        for (int j = 0; j < 8; j++) {
            const int col = mbe * MT + j * 8 + (lane & 3) * 2;
            if (c[j][0] < TH)
                atomicOr(&g_mask[(size_t)r0 * 64 + (col >> 5)], 1u << (col & 31));
            if (c[j][1] < TH)
                atomicOr(&g_mask[(size_t)r0 * 64 + ((col + 1) >> 5)],
                         1u << ((col + 1) & 31));
            if (c[j][2] < TH)
                atomicOr(&g_mask[(size_t)(r0 + 8) * 64 + (col >> 5)], 1u << (col & 31));
            if (c[j][3] < TH)
                atomicOr(&g_mask[(size_t)(r0 + 8) * 64 + ((col + 1) >> 5)],
                         1u << ((col + 1) & 31));
        }
    }
}

// ---- Kernel 5: exact refine of survivors, one warp per n ------------------
__global__ __launch_bounds__(256) void refine_kernel(const float* __restrict__ x,
                                                     const float* __restrict__ w,
                                                     float* __restrict__ out) {
    const int warp = threadIdx.x >> 5, lane = threadIdx.x & 31;
    const int n = blockIdx.x * 8 + warp;

    float xr[DD];
    {
        const float4* xp = reinterpret_cast<const float4*>(x + (size_t)n * DD);
#pragma unroll
        for (int i = 0; i < DD / 4; i++) {
            float4 v = __ldg(xp + i);
            xr[4 * i] = v.x; xr[4 * i + 1] = v.y;
            xr[4 * i + 2] = v.z; xr[4 * i + 3] = v.w;
        }
    }

    float acc = 0.0f;
#pragma unroll 1
    for (int wi = 0; wi < 2; wi++) {
        const int widx = wi * 32 + lane;
        uint32_t word = g_mask[(size_t)n * 64 + widx];
        while (word) {
            const int b = __ffs(word) - 1;
            word &= word - 1;
            const int m = widx * 32 + b;
            const float* blob = g_blob + (size_t)m * BLOB;
            const float4* t4 = reinterpret_cast<const float4*>(blob);

            float dist = __ldg(blob + 608);
#pragma unroll
            for (int d = 0; d < DD; d++) {
                float t0 = 0.0f, t1 = 0.0f, t2 = 0.0f, t3 = 0.0f;
                const int ro4 = rowstart(d) / 4;
#pragma unroll
                for (int g = 0; g < padlen(d) / 4; g++) {
                    float4 v = __ldg(t4 + ro4 + g);
                    const int e0 = d + 4 * g;
                    t0 += v.x * xr[e0];
                    if (e0 + 1 < DD) t1 += v.y * xr[e0 + 1];
                    if (e0 + 2 < DD) t2 += v.z * xr[e0 + 2];
                    if (e0 + 3 < DD) t3 += v.w * xr[e0 + 3];
                }
                dist += xr[d] * ((t0 + t1) + (t2 + t3));
            }
#pragma unroll
            for (int g = 0; g < DD / 4; g++) {
                float4 v = __ldg(t4 + 144 + g);
                dist += v.x * xr[4 * g] + v.y * xr[4 * g + 1] +
                        v.z * xr[4 * g + 2] + v.w * xr[4 * g + 3];
            }
            if (dist < 100.0f) acc += __ldg(w + m) * __expf(-dist);
        }
    }

#pragma unroll
    for (int s = 16; s > 0; s >>= 1) acc += __shfl_xor_sync(0xFFFFFFFFu, acc, s);
    if (lane == 0) out[n] = acc;
}

extern "C" void kernel_launch(void* const* d_in, const int* in_sizes, int n_in,
                              void* d_out, int out_size) {
    const float* inputs = (const float*)d_in[0];   // [N, D]
    const float* gamma = (const float*)d_in[1];    // [M, D, D]
    const float* means = (const float*)d_in[2];    // [M, D]
    const float* weights = (const float*)d_in[3];  // [M]
    float* out = (float*)d_out;                    // [N, 1]

    cudaFuncSetAttribute(screen_kernel, cudaFuncAttributeMaxDynamicSharedMemorySize,
                         DSMEM);

    prep_tri_kernel<<<1, KS>>>();
    prep_blob_kernel<<<MM, 128>>>(gamma, means);
    prep_a_kernel<<<NN / 4, 128>>>(inputs);
    zero_mask_kernel<<<(NN * (MM / 32)) / 1024, 1024>>>();
    screen_kernel<<<NN / NT, 256, DSMEM>>>();
    refine_kernel<<<NN / 8, 256>>>(inputs, weights, out);
}